// round 11
// baseline (speedup 1.0000x reference)
#include <cuda_runtime.h>
#include <mma.h>
#include <math.h>
#include <stdint.h>
#include <cstdint>

using namespace nvcuda;

#define BB 64
#define TT 256
#define DD 512
#define HH 1024
#define G4 4096
#define OO 512
#define NBLK 128
#define REC_THR 512
#define MROWS (BB*TT)   // 16384

// ---------------- scratch (device globals: allocation-free rule) -----------
__device__ float g_xz[(size_t)MROWS * G4];     // 256 MB
__device__ float g_seq1[(size_t)MROWS * HH];   // 64 MB, [t][b][h]
__device__ float g_Wt[(size_t)HH * G4];        // tf32-truncated W
__device__ float g_hA[BB * HH];
__device__ float g_hB[BB * HH];
__device__ unsigned g_count = 0;
__device__ volatile unsigned g_gen = 0;

__device__ __forceinline__ float to_tf32(float x) {
    float r; asm("cvt.rna.tf32.f32 %0, %1;" : "=f"(r) : "f"(x)); return r;
}

// raw tf32 mma m16n8k8 (legacy HMMA path, valid on sm_103 target)
__device__ __forceinline__ void mma_tf32(float* c,
    float a0, float a1, float a2, float a3, float b0, float b1)
{
    asm volatile(
        "mma.sync.aligned.m16n8k8.row.col.f32.tf32.tf32.f32 "
        "{%0,%1,%2,%3}, {%4,%5,%6,%7}, {%8,%9}, {%0,%1,%2,%3};"
        : "+f"(c[0]), "+f"(c[1]), "+f"(c[2]), "+f"(c[3])
        : "r"(__float_as_uint(a0)), "r"(__float_as_uint(a1)),
          "r"(__float_as_uint(a2)), "r"(__float_as_uint(a3)),
          "r"(__float_as_uint(b0)), "r"(__float_as_uint(b1)));
}

// dynamic smem for lstm_rec (floats): Upk[32768] + zs[8*64*34]
#define UPK_FLOATS 32768
#define ZS_STRIDE  34
#define ZS_FLOATS  (8 * 64 * ZS_STRIDE)
#define REC_SMEM_BYTES ((UPK_FLOATS + ZS_FLOATS) * 4)   // 200704

// ---------------- full software grid barrier (init only) -------------------
__device__ __forceinline__ void grid_barrier() {
    __syncthreads();
    if (threadIdx.x == 0) {
        __threadfence();
        unsigned gen = g_gen;
        if (atomicAdd(&g_count, 1u) == NBLK - 1u) {
            g_count = 0u;
            __threadfence();
            g_gen = gen + 1u;
        } else {
            while (g_gen == gen) {}
        }
        __threadfence();
    }
    __syncthreads();
}

// ---------------- tf32 pre-truncation of weights (input GEMM B) ------------
__global__ void trunc_kernel(const float* __restrict__ in,
                             float* __restrict__ out, int n4)
{
    int i = blockIdx.x * blockDim.x + threadIdx.x;
    if (i < n4) {
        float4 v = ((const float4*)in)[i];
        v.x = to_tf32(v.x); v.y = to_tf32(v.y);
        v.z = to_tf32(v.z); v.w = to_tf32(v.w);
        ((float4*)out)[i] = v;
    }
}

// ---------------------------------------------------------------------------
// Input GEMM (frozen from round 5)
// ---------------------------------------------------------------------------
template<int REMAP>
__global__ __launch_bounds__(256) void input_gemm(
    const float* __restrict__ A, const float* __restrict__ Bt,
    float* __restrict__ C, int K)
{
    __shared__ __align__(16) float As[2][128][20];
    __shared__ __align__(16) float Bs[2][16][136];
    const int tid = threadIdx.x;
    const int wid = tid >> 5;
    const int wr = wid >> 2;
    const int wc = wid & 3;
    const int r0 = blockIdx.y * 128, n0 = blockIdx.x * 128;

    wmma::fragment<wmma::accumulator, 16, 16, 8, float> c[4][2];
#pragma unroll
    for (int i = 0; i < 4; i++)
#pragma unroll
        for (int j = 0; j < 2; j++) wmma::fill_fragment(c[i][j], 0.f);

    const int arow = tid >> 1, ac8 = (tid & 1) * 8;
    const int rr = r0 + arow;
    const size_t gr = REMAP ? ((size_t)(rr & 63) * TT + (rr >> 6)) : (size_t)rr;
    const float* aptr = A + gr * K + ac8;
    const int brow = tid >> 4, bc8 = (tid & 15) * 8;
    const float* bptr = Bt + (size_t)brow * G4 + n0 + bc8;

    float4 a0, a1, b0, b1;

#define LOADK(kc)                                                   \
    do {                                                            \
        a0 = *(const float4*)(aptr + (kc));                         \
        a1 = *(const float4*)(aptr + (kc) + 4);                     \
        b0 = *(const float4*)(bptr + (size_t)(kc) * G4);            \
        b1 = *(const float4*)(bptr + (size_t)(kc) * G4 + 4);        \
    } while (0)

#define STOREK(s)                                                   \
    do {                                                            \
        As[s][arow][ac8 + 0] = to_tf32(a0.x);                       \
        As[s][arow][ac8 + 1] = to_tf32(a0.y);                       \
        As[s][arow][ac8 + 2] = to_tf32(a0.z);                       \
        As[s][arow][ac8 + 3] = to_tf32(a0.w);                       \
        As[s][arow][ac8 + 4] = to_tf32(a1.x);                       \
        As[s][arow][ac8 + 5] = to_tf32(a1.y);                       \
        As[s][arow][ac8 + 6] = to_tf32(a1.z);                       \
        As[s][arow][ac8 + 7] = to_tf32(a1.w);                       \
        *(float4*)&Bs[s][brow][bc8]     = b0;                       \
        *(float4*)&Bs[s][brow][bc8 + 4] = b1;                       \
    } while (0)

    LOADK(0);
    STOREK(0);
    __syncthreads();

    int s = 0;
    for (int kc = 0; kc < K; kc += 16) {
        const int nxt = kc + 16;
        if (nxt < K) LOADK(nxt);
#pragma unroll
        for (int kk = 0; kk < 2; kk++) {
            wmma::fragment<wmma::matrix_a, 16, 16, 8, wmma::precision::tf32, wmma::row_major> af[4];
            wmma::fragment<wmma::matrix_b, 16, 16, 8, wmma::precision::tf32, wmma::row_major> bf[2];
#pragma unroll
            for (int i = 0; i < 4; i++)
                wmma::load_matrix_sync(af[i], &As[s][wr * 64 + i * 16][kk * 8], 20);
#pragma unroll
            for (int j = 0; j < 2; j++)
                wmma::load_matrix_sync(bf[j], &Bs[s][kk * 8][wc * 32 + j * 16], 136);
#pragma unroll
            for (int i = 0; i < 4; i++)
#pragma unroll
                for (int j = 0; j < 2; j++)
                    wmma::mma_sync(c[i][j], af[i], bf[j], c[i][j]);
        }
        if (nxt < K) STOREK(s ^ 1);
        s ^= 1;
        __syncthreads();
    }
#undef LOADK
#undef STOREK

#pragma unroll
    for (int i = 0; i < 4; i++)
#pragma unroll
        for (int j = 0; j < 2; j++)
            wmma::store_matrix_sync(
                C + (size_t)(r0 + wr * 64 + i * 16) * G4 + n0 + wc * 32 + j * 16,
                c[i][j], G4, wmma::mem_row_major);
}

// ---------------------------------------------------------------------------
// Persistent recurrent layer v5 (raw mma, no A staging).
//   16 warps = 2 m-tiles (32 rows) x 8 k-splits (128 k each).
//   A (h) loaded straight from L2 into fragment regs (__ldcg scalars).
//   U packed in smem in exact b-fragment order -> one LDS.64 per B frag.
//   Partials (8 k-splits) reduced in the gate phase via zs.
// ---------------------------------------------------------------------------
template<bool WRITE_SEQ>
__global__ __launch_bounds__(REC_THR) void lstm_rec(
    const float* __restrict__ xz,   // [t*64+b][4096]
    const float* __restrict__ U,    // [1024][4096] raw fp32
    const float* __restrict__ bias, // [4096]
    float* __restrict__ seq_out)    // [t*64+b][1024] or null
{
    extern __shared__ __align__(16) float smem[];
    float* Upk = smem;               // [128 k8][4 n8][64] packed b-frags
    float* zs  = smem + UPK_FLOATS;  // [8][64][34]

    const int tid  = threadIdx.x;
    const int wid  = tid >> 5;
    const int lane = tid & 31;
    const int u0   = blockIdx.x * 8;
    const int wm   = wid & 1;        // m-tile: rows wm*32 .. wm*32+31
    const int ks   = wid >> 1;       // k-split: k  ks*128 .. +127

    // ---- one-time: pack U slice into b-fragment order (tf32) -------------
    for (int i = tid; i < UPK_FLOATS; i += REC_THR) {
        int k = i >> 5, c = i & 31;
        int k8t = k >> 3, kin = k & 7;
        int n8 = c >> 3, cin = c & 7;
        int pl = cin * 4 + (kin & 3);
        int pos = ((k8t * 4 + n8) << 6) + pl * 2 + (kin >> 2);
        Upk[pos] = to_tf32(__ldg(&U[(size_t)k * G4 + n8 * HH + u0 + cin]));
    }

    // ---- gate state -------------------------------------------------------
    const int gb = tid >> 3, gu = tid & 7;
    float creg = 0.f;
    float bg[4];
#pragma unroll
    for (int g = 0; g < 4; g++)
        bg[g] = __ldg(&bias[g * HH + u0 + gu]);
    g_hA[gb * HH + u0 + gu] = 0.f;

    float xzv[4];
#pragma unroll
    for (int g = 0; g < 4; g++)
        xzv[g] = __ldcg(&xz[(size_t)gb * G4 + g * HH + u0 + gu]);

    grid_barrier();

    // A-fragment addressing
    const int arow = wm * 32 + (lane >> 2);
    const int akol = ks * 128 + (lane & 3);

    for (int t = 0; t < TT; t++) {
        const float* hp = (t & 1) ? g_hB : g_hA;
        float*       hn = (t & 1) ? g_hA : g_hB;

        float C[2][4][4];
#pragma unroll
        for (int m = 0; m < 2; m++)
#pragma unroll
            for (int n = 0; n < 4; n++)
#pragma unroll
                for (int r = 0; r < 4; r++) C[m][n][r] = 0.f;

        const float* ab = hp + (size_t)arow * HH + akol;

        // double-buffered A fragments straight from L2
        float av[2][8];
#define LDA(dst, s) do {                                   \
        const float* p = ab + (s) * 8;                     \
        dst[0] = __ldcg(p);                                \
        dst[1] = __ldcg(p + 8 * HH);                       \
        dst[2] = __ldcg(p + 4);                            \
        dst[3] = __ldcg(p + 8 * HH + 4);                   \
        dst[4] = __ldcg(p + 16 * HH);                      \
        dst[5] = __ldcg(p + 24 * HH);                      \
        dst[6] = __ldcg(p + 16 * HH + 4);                  \
        dst[7] = __ldcg(p + 24 * HH + 4);                  \
    } while (0)

        LDA(av[0], 0);
#pragma unroll
        for (int s = 0; s < 16; s++) {
            const int cur = s & 1;
            if (s < 15) LDA(av[cur ^ 1], s + 1);
            const float* bt = Upk + (((ks * 16 + s) * 4) << 6) + lane * 2;
            float2 b0 = *(const float2*)(bt);
            float2 b1 = *(const float2*)(bt + 64);
            float2 b2 = *(const float2*)(bt + 128);
            float2 b3 = *(const float2*)(bt + 192);
            mma_tf32(C[0][0], av[cur][0], av[cur][1], av[cur][2], av[cur][3], b0.x, b0.y);
            mma_tf32(C[0][1], av[cur][0], av[cur][1], av[cur][2], av[cur][3], b1.x, b1.y);
            mma_tf32(C[0][2], av[cur][0], av[cur][1], av[cur][2], av[cur][3], b2.x, b2.y);
            mma_tf32(C[0][3], av[cur][0], av[cur][1], av[cur][2], av[cur][3], b3.x, b3.y);
            mma_tf32(C[1][0], av[cur][4], av[cur][5], av[cur][6], av[cur][7], b0.x, b0.y);
            mma_tf32(C[1][1], av[cur][4], av[cur][5], av[cur][6], av[cur][7], b1.x, b1.y);
            mma_tf32(C[1][2], av[cur][4], av[cur][5], av[cur][6], av[cur][7], b2.x, b2.y);
            mma_tf32(C[1][3], av[cur][4], av[cur][5], av[cur][6], av[cur][7], b3.x, b3.y);
        }
#undef LDA

        // ---- epilogue: store partials ------------------------------------
        {
            float* zp = zs + ks * (64 * ZS_STRIDE);
#pragma unroll
            for (int m = 0; m < 2; m++) {
                int row = wm * 32 + m * 16 + (lane >> 2);
#pragma unroll
                for (int n = 0; n < 4; n++) {
                    int col = n * 8 + (lane & 3) * 2;
                    *(float2*)&zp[row * ZS_STRIDE + col] =
                        make_float2(C[m][n][0], C[m][n][1]);
                    *(float2*)&zp[(row + 8) * ZS_STRIDE + col] =
                        make_float2(C[m][n][2], C[m][n][3]);
                }
            }
        }
        __syncthreads();

        // ---- fused gates (one (b,u) pair per thread) ---------------------
        {
            float z[4];
#pragma unroll
            for (int g = 0; g < 4; g++) {
                float v = xzv[g] + bg[g];
#pragma unroll
                for (int p = 0; p < 8; p++)
                    v += zs[p * (64 * ZS_STRIDE) + gb * ZS_STRIDE + g * 8 + gu];
                z[g] = v;
            }
            float ig = 1.f / (1.f + expf(-z[0]));
            float fg = 1.f / (1.f + expf(-z[1]));
            float og = 1.f / (1.f + expf(-z[3]));
            float cn = fg * creg + ig * tanhf(z[2]);
            float hv = og * tanhf(cn);
            creg = cn;
            hn[gb * HH + u0 + gu] = to_tf32(hv);
            if (WRITE_SEQ)
                seq_out[((size_t)t * BB + gb) * HH + u0 + gu] = hv;
        }

        // ---- split-phase grid barrier with xz prefetch overlap -----------
        __syncthreads();
        unsigned gn0 = 0;
        if (tid == 0) {
            __threadfence();
            gn0 = g_gen;
            if (atomicAdd(&g_count, 1u) == NBLK - 1u) {
                g_count = 0u;
                __threadfence();
                g_gen = gn0 + 1u;
            }
        }
        if (t + 1 < TT) {
            const float* xzr = xz + ((size_t)(t + 1) * BB + gb) * G4;
#pragma unroll
            for (int g = 0; g < 4; g++)
                xzv[g] = __ldcg(&xzr[g * HH + u0 + gu]);
        }
        if (tid == 0) {
            while (g_gen == gn0) {}
            __threadfence();
        }
        __syncthreads();
    }
}

// ---------------------------------------------------------------------------
// Final dense: out[b][o] = h_final[b][:] . Wd[:,o] + bd[o]  (h_final = g_hA)
// ---------------------------------------------------------------------------
__global__ __launch_bounds__(OO) void dense_kernel(
    const float* __restrict__ Wd, const float* __restrict__ bd,
    float* __restrict__ out)
{
    __shared__ float hs[HH];
    int b = blockIdx.x;
    int o = threadIdx.x;
    for (int k = o; k < HH; k += OO) hs[k] = g_hA[(size_t)b * HH + k];
    __syncthreads();
    float acc = 0.f;
#pragma unroll 8
    for (int k = 0; k < HH; k++)
        acc += hs[k] * __ldg(&Wd[(size_t)k * OO + o]);
    out[(size_t)b * OO + o] = acc + bd[o];
}

// ---------------------------------------------------------------------------
extern "C" void kernel_launch(void* const* d_in, const int* in_sizes, int n_in,
                              void* d_out, int out_size)
{
    const float* x  = (const float*)d_in[0];
    const float* W1 = (const float*)d_in[1];
    const float* U1 = (const float*)d_in[2];
    const float* b1 = (const float*)d_in[3];
    const float* W2 = (const float*)d_in[4];
    const float* U2 = (const float*)d_in[5];
    const float* b2 = (const float*)d_in[6];
    const float* Wd = (const float*)d_in[7];
    const float* bd = (const float*)d_in[8];
    float* out = (float*)d_out;

    float *xz, *seq1, *Wt;
    cudaGetSymbolAddress((void**)&xz,   g_xz);
    cudaGetSymbolAddress((void**)&seq1, g_seq1);
    cudaGetSymbolAddress((void**)&Wt,   g_Wt);

    cudaFuncSetAttribute(lstm_rec<true>,
        cudaFuncAttributeMaxDynamicSharedMemorySize, REC_SMEM_BYTES);
    cudaFuncSetAttribute(lstm_rec<false>,
        cudaFuncAttributeMaxDynamicSharedMemorySize, REC_SMEM_BYTES);

    // ---- layer 1 ----
    trunc_kernel<<<(DD * G4 / 4 + 255) / 256, 256>>>(W1, Wt, DD * G4 / 4);
    input_gemm<1><<<dim3(G4 / 128, MROWS / 128), 256>>>(x, Wt, xz, DD);
    lstm_rec<true><<<NBLK, REC_THR, REC_SMEM_BYTES>>>(xz, U1, b1, seq1);

    // ---- layer 2 ----
    trunc_kernel<<<(HH * G4 / 4 + 255) / 256, 256>>>(W2, Wt, HH * G4 / 4);
    input_gemm<0><<<dim3(G4 / 128, MROWS / 128), 256>>>(seq1, Wt, xz, HH);
    lstm_rec<false><<<NBLK, REC_THR, REC_SMEM_BYTES>>>(xz, U2, b2, nullptr);

    // ---- dense head ----
    dense_kernel<<<BB, OO>>>(Wd, bd, out);
}

// round 13
// speedup vs baseline: 1.5411x; 1.5411x over previous
#include <cuda_runtime.h>
#include <mma.h>
#include <math.h>
#include <stdint.h>
#include <cstdint>

using namespace nvcuda;

#define BB 64
#define TT 256
#define DD 512
#define HH 1024
#define G4 4096
#define OO 512
#define NBLK 128
#define REC_THR 256
#define MROWS (BB*TT)   // 16384

// ---------------- scratch (device globals: allocation-free rule) -----------
__device__ float g_xz[(size_t)MROWS * G4];     // 256 MB
__device__ float g_seq1[(size_t)MROWS * HH];   // 64 MB, [t][b][h]
__device__ float g_Wt[(size_t)HH * G4];        // tf32-truncated W
__device__ float g_hA[BB * HH];
__device__ float g_hB[BB * HH];
__device__ unsigned g_count = 0;
__device__ volatile unsigned g_gen = 0;

__device__ __forceinline__ float to_tf32(float x) {
    float r; asm("cvt.rna.tf32.f32 %0, %1;" : "=f"(r) : "f"(x)); return r;
}
__device__ __forceinline__ uint32_t smem_u32(const void* p) {
    uint32_t a;
    asm("{ .reg .u64 t; cvta.to.shared.u64 t, %1; cvt.u32.u64 %0, t; }"
        : "=r"(a) : "l"(p));
    return a;
}

// raw tf32 mma m16n8k8 (legacy HMMA path, valid on sm_103 target)
__device__ __forceinline__ void mma_tf32(float* c,
    float a0, float a1, float a2, float a3, float b0, float b1)
{
    asm volatile(
        "mma.sync.aligned.m16n8k8.row.col.f32.tf32.tf32.f32 "
        "{%0,%1,%2,%3}, {%4,%5,%6,%7}, {%8,%9}, {%0,%1,%2,%3};"
        : "+f"(c[0]), "+f"(c[1]), "+f"(c[2]), "+f"(c[3])
        : "r"(__float_as_uint(a0)), "r"(__float_as_uint(a1)),
          "r"(__float_as_uint(a2)), "r"(__float_as_uint(a3)),
          "r"(__float_as_uint(b0)), "r"(__float_as_uint(b1)));
}

// lstm_rec smem: 2 h-chunk buffers [64][260] + zs [8][64][40]
#define BUF_FLOATS 16640           // 64*260
#define ZS_STRIDE  40
#define ZS_OFF     (2 * BUF_FLOATS)              // 33280 floats
#define REC_SMEM_BYTES ((ZS_OFF + 8 * 64 * ZS_STRIDE) * 4)   // 215040

// ---------------- full software grid barrier (init only) -------------------
__device__ __forceinline__ void grid_barrier() {
    __syncthreads();
    if (threadIdx.x == 0) {
        __threadfence();
        unsigned gen = g_gen;
        if (atomicAdd(&g_count, 1u) == NBLK - 1u) {
            g_count = 0u;
            __threadfence();
            g_gen = gen + 1u;
        } else {
            while (g_gen == gen) {}
        }
        __threadfence();
    }
    __syncthreads();
}

// ---------------- tf32 pre-truncation of weights (input GEMM B) ------------
__global__ void trunc_kernel(const float* __restrict__ in,
                             float* __restrict__ out, int n4)
{
    int i = blockIdx.x * blockDim.x + threadIdx.x;
    if (i < n4) {
        float4 v = ((const float4*)in)[i];
        v.x = to_tf32(v.x); v.y = to_tf32(v.y);
        v.z = to_tf32(v.z); v.w = to_tf32(v.w);
        ((float4*)out)[i] = v;
    }
}

// ---------------------------------------------------------------------------
// Input GEMM (frozen from round 5)
// ---------------------------------------------------------------------------
template<int REMAP>
__global__ __launch_bounds__(256) void input_gemm(
    const float* __restrict__ A, const float* __restrict__ Bt,
    float* __restrict__ C, int K)
{
    __shared__ __align__(16) float As[2][128][20];
    __shared__ __align__(16) float Bs[2][16][136];
    const int tid = threadIdx.x;
    const int wid = tid >> 5;
    const int wr = wid >> 2;
    const int wc = wid & 3;
    const int r0 = blockIdx.y * 128, n0 = blockIdx.x * 128;

    wmma::fragment<wmma::accumulator, 16, 16, 8, float> c[4][2];
#pragma unroll
    for (int i = 0; i < 4; i++)
#pragma unroll
        for (int j = 0; j < 2; j++) wmma::fill_fragment(c[i][j], 0.f);

    const int arow = tid >> 1, ac8 = (tid & 1) * 8;
    const int rr = r0 + arow;
    const size_t gr = REMAP ? ((size_t)(rr & 63) * TT + (rr >> 6)) : (size_t)rr;
    const float* aptr = A + gr * K + ac8;
    const int brow = tid >> 4, bc8 = (tid & 15) * 8;
    const float* bptr = Bt + (size_t)brow * G4 + n0 + bc8;

    float4 a0, a1, b0, b1;

#define LOADK(kc)                                                   \
    do {                                                            \
        a0 = *(const float4*)(aptr + (kc));                         \
        a1 = *(const float4*)(aptr + (kc) + 4);                     \
        b0 = *(const float4*)(bptr + (size_t)(kc) * G4);            \
        b1 = *(const float4*)(bptr + (size_t)(kc) * G4 + 4);        \
    } while (0)

#define STOREK(s)                                                   \
    do {                                                            \
        As[s][arow][ac8 + 0] = to_tf32(a0.x);                       \
        As[s][arow][ac8 + 1] = to_tf32(a0.y);                       \
        As[s][arow][ac8 + 2] = to_tf32(a0.z);                       \
        As[s][arow][ac8 + 3] = to_tf32(a0.w);                       \
        As[s][arow][ac8 + 4] = to_tf32(a1.x);                       \
        As[s][arow][ac8 + 5] = to_tf32(a1.y);                       \
        As[s][arow][ac8 + 6] = to_tf32(a1.z);                       \
        As[s][arow][ac8 + 7] = to_tf32(a1.w);                       \
        *(float4*)&Bs[s][brow][bc8]     = b0;                       \
        *(float4*)&Bs[s][brow][bc8 + 4] = b1;                       \
    } while (0)

    LOADK(0);
    STOREK(0);
    __syncthreads();

    int s = 0;
    for (int kc = 0; kc < K; kc += 16) {
        const int nxt = kc + 16;
        if (nxt < K) LOADK(nxt);
#pragma unroll
        for (int kk = 0; kk < 2; kk++) {
            wmma::fragment<wmma::matrix_a, 16, 16, 8, wmma::precision::tf32, wmma::row_major> af[4];
            wmma::fragment<wmma::matrix_b, 16, 16, 8, wmma::precision::tf32, wmma::row_major> bf[2];
#pragma unroll
            for (int i = 0; i < 4; i++)
                wmma::load_matrix_sync(af[i], &As[s][wr * 64 + i * 16][kk * 8], 20);
#pragma unroll
            for (int j = 0; j < 2; j++)
                wmma::load_matrix_sync(bf[j], &Bs[s][kk * 8][wc * 32 + j * 16], 136);
#pragma unroll
            for (int i = 0; i < 4; i++)
#pragma unroll
                for (int j = 0; j < 2; j++)
                    wmma::mma_sync(c[i][j], af[i], bf[j], c[i][j]);
        }
        if (nxt < K) STOREK(s ^ 1);
        s ^= 1;
        __syncthreads();
    }
#undef LOADK
#undef STOREK

#pragma unroll
    for (int i = 0; i < 4; i++)
#pragma unroll
        for (int j = 0; j < 2; j++)
            wmma::store_matrix_sync(
                C + (size_t)(r0 + wr * 64 + i * 16) * G4 + n0 + wc * 32 + j * 16,
                c[i][j], G4, wmma::mem_row_major);
}

// ---------------------------------------------------------------------------
// Persistent recurrent layer v6 (fixed staging).
//   256 threads, 8 warps. U (32 cols x 1024 k) permanently in registers.
//   h staged via cp.async in 4 x 64KB chunks (4096 float4 each, 16/thread),
//   double-buffered. Warp w covers k-subrange [w*32, w*32+32) of each chunk.
// ---------------------------------------------------------------------------
template<bool WRITE_SEQ>
__global__ __launch_bounds__(REC_THR, 1) void lstm_rec(
    const float* __restrict__ xz,   // [t*64+b][4096]
    const float* __restrict__ U,    // [1024][4096] raw fp32
    const float* __restrict__ bias, // [4096]
    float* __restrict__ seq_out)    // [t*64+b][1024] or null
{
    extern __shared__ __align__(16) float smem[];
    float* zsb = smem + ZS_OFF;     // [8][64][40]

    const int tid  = threadIdx.x;
    const int w    = tid >> 5;
    const int lane = tid & 31;
    const int u0   = blockIdx.x * 8;
    const int lq   = lane >> 2;     // quad id 0..7
    const int lr   = lane & 3;      // in-quad 0..3

    // ---- one-time: load U b-fragments into registers (tf32) --------------
    float breg[128];    // index ((c*4+q)*4 + j)*2 + r
#pragma unroll
    for (int c = 0; c < 4; c++)
#pragma unroll
        for (int q = 0; q < 4; q++)
#pragma unroll
            for (int j = 0; j < 4; j++)
#pragma unroll
                for (int r = 0; r < 2; r++) {
                    int kg = c * 256 + w * 32 + q * 8 + r * 4 + lr;
                    breg[((c * 4 + q) * 4 + j) * 2 + r] =
                        to_tf32(__ldg(&U[(size_t)kg * G4 + j * HH + u0 + lq]));
                }

    // ---- gate state: 2 (b,unit) pairs per thread -------------------------
    float creg[2] = {0.f, 0.f};
    float bg[2][4], xzv[2][4];
#pragma unroll
    for (int i = 0; i < 2; i++) {
        int p = tid + i * 256;
        int b = p >> 3, uu = p & 7;
        g_hA[b * HH + u0 + uu] = 0.f;
#pragma unroll
        for (int g = 0; g < 4; g++) {
            bg[i][g]  = __ldg(&bias[g * HH + u0 + uu]);
            xzv[i][g] = __ldcg(&xz[(size_t)b * G4 + g * HH + u0 + uu]);
        }
    }
    grid_barrier();

    const uint32_t sb0 = smem_u32(smem);

    for (int t = 0; t < TT; t++) {
        const float* hp = (t & 1) ? g_hB : g_hA;
        float*       hn = (t & 1) ? g_hA : g_hB;

        float C[4][4][4];
#pragma unroll
        for (int m = 0; m < 4; m++)
#pragma unroll
            for (int j = 0; j < 4; j++)
#pragma unroll
                for (int r = 0; r < 4; r++) C[m][j][r] = 0.f;

        // stage one chunk: 64 rows x 256 k = 4096 float4s, 16 per thread
#define CP_ISSUE(cc)                                                          \
        do {                                                                  \
            uint32_t dbase = sb0 + ((cc) & 1) * (BUF_FLOATS * 4);             \
            _Pragma("unroll")                                                 \
            for (int it = 0; it < 16; it++) {                                 \
                int idx = tid + it * 256;                                     \
                int row = idx >> 6, qq = idx & 63;                            \
                uint32_t d = dbase + (uint32_t)(row * 260 + qq * 4) * 4;      \
                const float* sgp = hp + (size_t)row * HH + (cc) * 256 + qq * 4; \
                asm volatile("cp.async.cg.shared.global [%0], [%1], 16;"      \
                             :: "r"(d), "l"(sgp));                            \
            }                                                                 \
            asm volatile("cp.async.commit_group;" ::: "memory");              \
        } while (0)

        CP_ISSUE(0);
        CP_ISSUE(1);

#pragma unroll
        for (int c = 0; c < 4; c++) {
            if (c < 3) asm volatile("cp.async.wait_group 1;" ::: "memory");
            else       asm volatile("cp.async.wait_group 0;" ::: "memory");
            __syncthreads();
            const float* bufc = smem + (c & 1) * BUF_FLOATS;
#pragma unroll
            for (int q = 0; q < 4; q++) {
                const int kb = w * 32 + q * 8 + lr;
#pragma unroll
                for (int m = 0; m < 4; m++) {
                    const int r0 = m * 16 + lq;
                    float a0 = bufc[r0 * 260 + kb];
                    float a1 = bufc[(r0 + 8) * 260 + kb];
                    float a2 = bufc[r0 * 260 + kb + 4];
                    float a3 = bufc[(r0 + 8) * 260 + kb + 4];
#pragma unroll
                    for (int j = 0; j < 4; j++)
                        mma_tf32(C[m][j], a0, a1, a2, a3,
                                 breg[((c * 4 + q) * 4 + j) * 2],
                                 breg[((c * 4 + q) * 4 + j) * 2 + 1]);
                }
            }
            if (c < 2) {
                __syncthreads();          // all warps done reading buf[c&1]
                CP_ISSUE(c + 2);
            }
        }
#undef CP_ISSUE

        // ---- epilogue: C -> zs partials ----------------------------------
        {
            float* zp = zsb + w * (64 * ZS_STRIDE);
#pragma unroll
            for (int m = 0; m < 4; m++) {
                int r0 = m * 16 + lq;
#pragma unroll
                for (int j = 0; j < 4; j++) {
                    int col = j * 8 + lr * 2;
                    *(float2*)&zp[r0 * ZS_STRIDE + col] =
                        make_float2(C[m][j][0], C[m][j][1]);
                    *(float2*)&zp[(r0 + 8) * ZS_STRIDE + col] =
                        make_float2(C[m][j][2], C[m][j][3]);
                }
            }
        }
        __syncthreads();

        // ---- fused gates (2 pairs per thread) ----------------------------
#pragma unroll
        for (int i = 0; i < 2; i++) {
            int p = tid + i * 256;
            int b = p >> 3, uu = p & 7;
            float z[4];
#pragma unroll
            for (int g = 0; g < 4; g++) {
                float v = xzv[i][g] + bg[i][g];
#pragma unroll
                for (int pw = 0; pw < 8; pw++)
                    v += zsb[pw * (64 * ZS_STRIDE) + b * ZS_STRIDE + g * 8 + uu];
                z[g] = v;
            }
            float ig = 1.f / (1.f + __expf(-z[0]));
            float fg = 1.f / (1.f + __expf(-z[1]));
            float og = 1.f / (1.f + __expf(-z[3]));
            float cn = fg * creg[i] + ig * tanhf(z[2]);
            float hv = og * tanhf(cn);
            creg[i] = cn;
            hn[b * HH + u0 + uu] = to_tf32(hv);
            if (WRITE_SEQ)
                seq_out[((size_t)t * BB + b) * HH + u0 + uu] = hv;
        }

        // ---- split-phase grid barrier with xz prefetch overlap -----------
        __syncthreads();
        unsigned gn0 = 0;
        if (tid == 0) {
            __threadfence();
            gn0 = g_gen;
            if (atomicAdd(&g_count, 1u) == NBLK - 1u) {
                g_count = 0u;
                __threadfence();
                g_gen = gn0 + 1u;
            }
        }
        if (t + 1 < TT) {
#pragma unroll
            for (int i = 0; i < 2; i++) {
                int p = tid + i * 256;
                int b = p >> 3, uu = p & 7;
                const float* xzr = xz + ((size_t)(t + 1) * BB + b) * G4;
#pragma unroll
                for (int g = 0; g < 4; g++)
                    xzv[i][g] = __ldcg(&xzr[g * HH + u0 + uu]);
            }
        }
        if (tid == 0) {
            while (g_gen == gn0) {}
            __threadfence();
        }
        __syncthreads();
    }
}

// ---------------------------------------------------------------------------
// Final dense: out[b][o] = h_final[b][:] . Wd[:,o] + bd[o]  (h_final = g_hA)
// ---------------------------------------------------------------------------
__global__ __launch_bounds__(OO) void dense_kernel(
    const float* __restrict__ Wd, const float* __restrict__ bd,
    float* __restrict__ out)
{
    __shared__ float hs[HH];
    int b = blockIdx.x;
    int o = threadIdx.x;
    for (int k = o; k < HH; k += OO) hs[k] = g_hA[(size_t)b * HH + k];
    __syncthreads();
    float acc = 0.f;
#pragma unroll 8
    for (int k = 0; k < HH; k++)
        acc += hs[k] * __ldg(&Wd[(size_t)k * OO + o]);
    out[(size_t)b * OO + o] = acc + bd[o];
}

// ---------------------------------------------------------------------------
extern "C" void kernel_launch(void* const* d_in, const int* in_sizes, int n_in,
                              void* d_out, int out_size)
{
    const float* x  = (const float*)d_in[0];
    const float* W1 = (const float*)d_in[1];
    const float* U1 = (const float*)d_in[2];
    const float* b1 = (const float*)d_in[3];
    const float* W2 = (const float*)d_in[4];
    const float* U2 = (const float*)d_in[5];
    const float* b2 = (const float*)d_in[6];
    const float* Wd = (const float*)d_in[7];
    const float* bd = (const float*)d_in[8];
    float* out = (float*)d_out;

    float *xz, *seq1, *Wt;
    cudaGetSymbolAddress((void**)&xz,   g_xz);
    cudaGetSymbolAddress((void**)&seq1, g_seq1);
    cudaGetSymbolAddress((void**)&Wt,   g_Wt);

    cudaFuncSetAttribute(lstm_rec<true>,
        cudaFuncAttributeMaxDynamicSharedMemorySize, REC_SMEM_BYTES);
    cudaFuncSetAttribute(lstm_rec<false>,
        cudaFuncAttributeMaxDynamicSharedMemorySize, REC_SMEM_BYTES);

    // ---- layer 1 ----
    trunc_kernel<<<(DD * G4 / 4 + 255) / 256, 256>>>(W1, Wt, DD * G4 / 4);
    input_gemm<1><<<dim3(G4 / 128, MROWS / 128), 256>>>(x, Wt, xz, DD);
    lstm_rec<true><<<NBLK, REC_THR, REC_SMEM_BYTES>>>(xz, U1, b1, seq1);

    // ---- layer 2 ----
    trunc_kernel<<<(HH * G4 / 4 + 255) / 256, 256>>>(W2, Wt, HH * G4 / 4);
    input_gemm<0><<<dim3(G4 / 128, MROWS / 128), 256>>>(seq1, Wt, xz, HH);
    lstm_rec<false><<<NBLK, REC_THR, REC_SMEM_BYTES>>>(xz, U2, b2, nullptr);

    // ---- dense head ----
    dense_kernel<<<BB, OO>>>(Wd, bd, out);
}